// round 16
// baseline (speedup 1.0000x reference)
#include <cuda_runtime.h>
#include <cstdint>

// HexPool: out[i, :] = max_{k<7} x[neigh_indices[i,k], :]
// x: (655362, 64) f32 ; neigh_indices: (163842, 7) int32 ; out: (163842, 64) f32
//
// Variant on the winning R7 shape: 16 threads (one half-warp) per output row,
// one float4 (LDG.128) per gather -- preserving the measured-best property
// that each gather warp-instruction touches only 2 distinct rows -- but each
// thread processes TWO output rows: r and r + 81921 (= N_OUT/2). Both rows'
// 7 gathers issue back-to-back: 14 independent LDG.128s per thread (2x R7's
// MLP) at identical per-instruction coalescing. Index fetch amortized: lanes
// 0-6 of each half-warp carry row A's indices, lanes 8-14 carry row B's.
// Output stores __stcs (streaming/evict-first) -- the reproducible -10% win.
// Tail: HALF_OUT*16 = 1,310,736 = 256*5120 + 16, so the last block has 240
// excess threads; they clamp rowA (duplicate work) and skip stores. All lanes
// stay converged through every __shfl_sync.

#define N_OUT 163842
#define HALF_OUT 81921            // N_OUT / 2, exact
#define KNB   7
#define VEC_PER_ROW 16            // 64 floats / 4
#define BLOCK_THREADS 256

__global__ __launch_bounds__(BLOCK_THREADS) void hexpool_kernel(
    const float4* __restrict__ x,          // viewed as [n_in][16] float4
    const int* __restrict__ idx,           // [N_OUT][7] int32
    float4* __restrict__ out)               // [N_OUT][16] float4
{
    const int gid = blockIdx.x * BLOCK_THREADS + threadIdx.x;
    const int rowA_raw = gid >> 4;
    const int rowA = rowA_raw < HALF_OUT ? rowA_raw : (HALF_OUT - 1);
    const int rowB = rowA + HALF_OUT;
    const int col  = gid & 15;             // float4 column within row

    const int lane = threadIdx.x & 31;
    const int half_base = lane & 16;       // 0 or 16: start lane of my half-warp
    const int sub = lane & 15;

    // Index fetch for BOTH rows with one predicated load per lane:
    // lanes sub 0..6  -> rowA's 7 indices ; lanes sub 8..14 -> rowB's 7.
    int my_idx = 0;
    if (sub < KNB) {
        my_idx = __ldg(&idx[rowA * KNB + sub]);
    } else if (sub >= 8 && sub < 8 + KNB) {
        my_idx = __ldg(&idx[rowB * KNB + (sub - 8)]);
    }

    const float NEG = -3.402823466e+38f;
    float4 mA = make_float4(NEG, NEG, NEG, NEG);
    float4 mB = make_float4(NEG, NEG, NEG, NEG);

    #pragma unroll
    for (int k = 0; k < KNB; ++k) {
        int jA = __shfl_sync(0xFFFFFFFFu, my_idx, half_base + k);
        int jB = __shfl_sync(0xFFFFFFFFu, my_idx, half_base + 8 + k);
        float4 vA = __ldg(&x[(long long)jA * VEC_PER_ROW + col]);
        float4 vB = __ldg(&x[(long long)jB * VEC_PER_ROW + col]);
        mA.x = fmaxf(mA.x, vA.x);  mA.y = fmaxf(mA.y, vA.y);
        mA.z = fmaxf(mA.z, vA.z);  mA.w = fmaxf(mA.w, vA.w);
        mB.x = fmaxf(mB.x, vB.x);  mB.y = fmaxf(mB.y, vB.y);
        mB.z = fmaxf(mB.z, vB.z);  mB.w = fmaxf(mB.w, vB.w);
    }

    if (rowA_raw < HALF_OUT) {
        __stcs(&out[(long long)rowA * VEC_PER_ROW + col], mA);
        __stcs(&out[(long long)rowB * VEC_PER_ROW + col], mB);
    }
}

extern "C" void kernel_launch(void* const* d_in, const int* in_sizes, int n_in,
                              void* d_out, int out_size)
{
    const float4* x   = (const float4*)d_in[0];
    const int*    idx = (const int*)d_in[1];
    float4*       out = (float4*)d_out;

    const long long total_threads = (long long)HALF_OUT * VEC_PER_ROW; // 1,310,736
    const int grid = (int)((total_threads + BLOCK_THREADS - 1) / BLOCK_THREADS); // 5121
    hexpool_kernel<<<grid, BLOCK_THREADS>>>(x, idx, out);
}